// round 5
// baseline (speedup 1.0000x reference)
#include <cuda_runtime.h>
#include <mma.h>
#include <cstdint>

using namespace nvcuda;

// ---------------------------------------------------------------------------
// BBoxHead via legacy tensor-core tf32 WMMA GEMMs (compute_103-safe).
//   GEMM1: X[2000,12544] @ W1 -> x1[2000,1024] (+b1), BN+ReLU(+rna)
//   GEMM2: x1 @ W2 -> x2 (+b2), BN+ReLU(+rna)
//   HEADS: x2 @ [Wl|Wd] (N padded to 512) -> logits/deltas, softmax
// B operands pre-transposed to [N,K] K-major with cvt.rna.tf32.
// GEMM: 128x128 CTA tile, 4 warps, 64x64 warp tile (4x4 m16n16k8 frags).
// ---------------------------------------------------------------------------

#define N_ROI  2000
#define K1     12544
#define HID    1024
#define NCLS   81
#define NDEL   324
#define NHEAD  405
#define NHPAD  512
#define BN_EPS 1e-3f

__device__ float g_At  [N_ROI * K1];
__device__ float g_W1t [HID * K1];
__device__ float g_W2t [HID * HID];
__device__ float g_Wht [NHPAD * HID];
__device__ float g_bh  [NHPAD];
__device__ float g_x1  [2048 * HID];
__device__ float g_x2  [2048 * HID];
__device__ float g_heads[N_ROI * NHPAD];
__device__ float g_scale[HID];
__device__ float g_shift[HID];

// ---------------------------------------------------------------------------
__device__ __forceinline__ uint32_t smem_u32(const void* p) {
    uint32_t a;
    asm("{ .reg .u64 t; cvta.to.shared.u64 t, %1; cvt.u32.u64 %0, t; }" : "=r"(a) : "l"(p));
    return a;
}
__device__ __forceinline__ float rna_tf32(float x) {
    uint32_t r;
    asm("cvt.rna.tf32.f32 %0, %1;" : "=r"(r) : "f"(x));
    return __uint_as_float(r);
}
__device__ __forceinline__ void cp_async16(uint32_t saddr, const void* g, bool valid) {
    int sz = valid ? 16 : 0;
    asm volatile("cp.async.cg.shared.global [%0], [%1], 16, %2;"
                 :: "r"(saddr), "l"(g), "r"(sz) : "memory");
}
__device__ __forceinline__ void cp_commit() {
    asm volatile("cp.async.commit_group;" ::: "memory");
}
template<int N> __device__ __forceinline__ void cp_wait() {
    asm volatile("cp.async.wait_group %0;" :: "n"(N) : "memory");
}

// ---------------------------------------------------------------------------
#define LDT        36                    // 32 + 4 pad floats; row = 144 B
#define HALF_STAGE (128 * LDT * 4)       // 18432 B
#define STAGE_B    (2 * HALF_STAGE)
#define NSTAGE     3
#define SMEM_TOT   (NSTAGE * STAGE_B)    // 110592 B
#define LDE        132

// 128 threads: 1024 16B-chunks per tile -> 8 per thread
__device__ __forceinline__ void fill_tile(uint32_t sbase, const float* __restrict__ gb,
                                          int ldg, int row0, int maxrow, int k0, int tid) {
#pragma unroll
    for (int r = 0; r < 8; r++) {
        int id  = tid + r * 128;
        int row = id >> 3;
        int c16 = id & 7;
        uint32_t sa = sbase + row * (LDT * 4) + c16 * 16;
        const float* g = gb + (size_t)(row0 + row) * ldg + k0 + c16 * 4;
        cp_async16(sa, g, (row0 + row) < maxrow);
    }
}

__global__ __launch_bounds__(128)
void gemm_tf32(const float* __restrict__ A, const float* __restrict__ Bt,
               const float* __restrict__ bias, float* __restrict__ C,
               int M, int K, int ldC) {
    extern __shared__ float smem[];
    const uint32_t sb = smem_u32(smem);
    const int tid = threadIdx.x;
    const int wid = tid >> 5;
    const int row0 = blockIdx.y * 128;
    const int col0 = blockIdx.x * 128;
    const int warp_m = wid & 1;     // 0..1 -> 64-row strip
    const int warp_n = wid >> 1;    // 0..1 -> 64-col strip
    const int NK = K / 32;

    wmma::fragment<wmma::accumulator, 16, 16, 8, float> fc[4][4];
#pragma unroll
    for (int i = 0; i < 4; i++)
#pragma unroll
        for (int j = 0; j < 4; j++) wmma::fill_fragment(fc[i][j], 0.0f);

    // prologue: fill stages 0,1
    fill_tile(sb + 0 * STAGE_B,              A,  K, row0, M,       0,  tid);
    fill_tile(sb + 0 * STAGE_B + HALF_STAGE, Bt, K, col0, 1 << 30, 0,  tid);
    cp_commit();
    if (NK > 1) {
        fill_tile(sb + 1 * STAGE_B,              A,  K, row0, M,       32, tid);
        fill_tile(sb + 1 * STAGE_B + HALF_STAGE, Bt, K, col0, 1 << 30, 32, tid);
    }
    cp_commit();

    int s = 0;
    for (int i = 0; i < NK; i++) {
        cp_wait<1>();
        __syncthreads();

        const float* As = smem + s * (STAGE_B / 4);
        const float* Bs = As + (HALF_STAGE / 4);
        const float* Aw = As + (warp_m * 64) * LDT;
        const float* Bw = Bs + (warp_n * 64) * LDT;

#pragma unroll
        for (int ks = 0; ks < 4; ks++) {
            wmma::fragment<wmma::matrix_a, 16, 16, 8, wmma::precision::tf32, wmma::row_major> fa[4];
            wmma::fragment<wmma::matrix_b, 16, 16, 8, wmma::precision::tf32, wmma::col_major> fb[4];
#pragma unroll
            for (int ii = 0; ii < 4; ii++)
                wmma::load_matrix_sync(fa[ii], Aw + ii * 16 * LDT + ks * 8, LDT);
#pragma unroll
            for (int jj = 0; jj < 4; jj++)
                wmma::load_matrix_sync(fb[jj], Bw + jj * 16 * LDT + ks * 8, LDT);
#pragma unroll
            for (int ii = 0; ii < 4; ii++)
#pragma unroll
                for (int jj = 0; jj < 4; jj++)
                    wmma::mma_sync(fc[ii][jj], fa[ii], fb[jj], fc[ii][jj]);
        }

        if (i + 2 < NK) {
            int sn = (s + 2 >= NSTAGE) ? s + 2 - NSTAGE : s + 2;
            fill_tile(sb + sn * STAGE_B,              A,  K, row0, M,       (i + 2) * 32, tid);
            fill_tile(sb + sn * STAGE_B + HALF_STAGE, Bt, K, col0, 1 << 30, (i + 2) * 32, tid);
        }
        cp_commit();
        s = (s + 1 == NSTAGE) ? 0 : s + 1;
    }

    // epilogue: frags -> smem -> global (+bias), M-guarded, float4 stores
    cp_wait<0>();
    __syncthreads();
    float* esm = smem;   // 128 x LDE floats = 67584 B < SMEM_TOT
#pragma unroll
    for (int ii = 0; ii < 4; ii++)
#pragma unroll
        for (int jj = 0; jj < 4; jj++)
            wmma::store_matrix_sync(esm + (warp_m * 64 + ii * 16) * LDE + warp_n * 64 + jj * 16,
                                    fc[ii][jj], LDE, wmma::mem_row_major);
    __syncthreads();
#pragma unroll 4
    for (int e = tid; e < 128 * 32; e += 128) {
        int r  = e >> 5;
        int c4 = (e & 31) * 4;
        int gr = row0 + r;
        if (gr < M) {
            const float* sp = esm + r * LDE + c4;
            float4 v;
            v.x = sp[0] + bias[col0 + c4 + 0];
            v.y = sp[1] + bias[col0 + c4 + 1];
            v.z = sp[2] + bias[col0 + c4 + 2];
            v.w = sp[3] + bias[col0 + c4 + 3];
            *(float4*)&C[(size_t)gr * ldC + col0 + c4] = v;
        }
    }
}

// ---------------------------------------------------------------------------
// Prep kernels
// ---------------------------------------------------------------------------
__global__ void cvt_rna_copy(const float* __restrict__ in, float* __restrict__ out, int n4) {
    int i = blockIdx.x * blockDim.x + threadIdx.x;
    if (i < n4) {
        float4 v = ((const float4*)in)[i];
        v.x = rna_tf32(v.x); v.y = rna_tf32(v.y);
        v.z = rna_tf32(v.z); v.w = rna_tf32(v.w);
        ((float4*)out)[i] = v;
    }
}

__global__ void transpose_rna(const float* __restrict__ in, float* __restrict__ out,
                              int K, int Nc, int ldout, int row_off) {
    __shared__ float t[32][33];
    int k0 = blockIdx.x * 32, n0 = blockIdx.y * 32;
    int x = threadIdx.x, y = threadIdx.y;
#pragma unroll
    for (int yy = y; yy < 32; yy += 8) {
        int k = k0 + yy, n = n0 + x;
        t[yy][x] = (k < K && n < Nc) ? in[(size_t)k * Nc + n] : 0.f;
    }
    __syncthreads();
#pragma unroll
    for (int yy = y; yy < 32; yy += 8) {
        int n = n0 + yy, k = k0 + x;
        if (n < Nc && k < K)
            out[(size_t)(row_off + n) * ldout + k] = rna_tf32(t[x][yy]);
    }
}

// Fused transpose of [Wl | Wd] over combined N index 0..404 -> Wht rows.
__global__ void transpose_heads(const float* __restrict__ wl, const float* __restrict__ wd,
                                float* __restrict__ out) {
    __shared__ float t[32][33];
    int k0 = blockIdx.x * 32, n0 = blockIdx.y * 32;
    int x = threadIdx.x, y = threadIdx.y;
#pragma unroll
    for (int yy = y; yy < 32; yy += 8) {
        int k = k0 + yy, n = n0 + x;
        float v = 0.f;
        if (n < NHEAD) {
            v = (n < NCLS) ? wl[(size_t)k * NCLS + n]
                           : wd[(size_t)k * NDEL + (n - NCLS)];
        }
        t[yy][x] = v;
    }
    __syncthreads();
#pragma unroll
    for (int yy = y; yy < 32; yy += 8) {
        int n = n0 + yy, k = k0 + x;
        if (n < NHEAD)
            out[(size_t)n * HID + k] = rna_tf32(t[x][yy]);
    }
}

__global__ void head_pad_init(const float* __restrict__ bl, const float* __restrict__ bd,
                              float* __restrict__ bh, float* __restrict__ wht) {
    int i = blockIdx.x * blockDim.x + threadIdx.x;
    if (i < NHPAD)
        bh[i] = (i < NCLS) ? bl[i] : (i < NHEAD ? bd[i - NCLS] : 0.f);
    for (int j = i; j < (NHPAD - NHEAD) * HID; j += gridDim.x * blockDim.x)
        wht[(size_t)NHEAD * HID + j] = 0.f;
}

// ---------------------------------------------------------------------------
// BN / activation / heads epilogue
// ---------------------------------------------------------------------------
__global__ void bn_stats_kernel(const float* __restrict__ x,
                                const float* __restrict__ gamma,
                                const float* __restrict__ beta,
                                float* __restrict__ scale, float* __restrict__ shift,
                                int M, int N) {
    int col = blockIdx.x * 32 + threadIdx.x;
    float s = 0.f, sq = 0.f;
    for (int r = threadIdx.y; r < M; r += blockDim.y) {
        float v = x[(size_t)r * N + col];
        s += v; sq += v * v;
    }
    __shared__ float ss[8][32], sg[8][32];
    ss[threadIdx.y][threadIdx.x] = s;
    sg[threadIdx.y][threadIdx.x] = sq;
    __syncthreads();
    if (threadIdx.y == 0) {
#pragma unroll
        for (int i = 1; i < 8; i++) { s += ss[i][threadIdx.x]; sq += sg[i][threadIdx.x]; }
        float mean = s / (float)M;
        float var  = sq / (float)M - mean * mean;
        float sc   = gamma[col] * rsqrtf(var + BN_EPS);
        scale[col] = sc;
        shift[col] = beta[col] - mean * sc;
    }
}

__global__ void bn_relu_rna_kernel(float* __restrict__ x, const float* __restrict__ scale,
                                   const float* __restrict__ shift, int total, int N) {
    int i = blockIdx.x * blockDim.x + threadIdx.x;
    if (i < total) {
        int c = i & (N - 1);
        x[i] = rna_tf32(fmaxf(0.f, fmaf(x[i], scale[c], shift[c])));
    }
}

__global__ void scatter_heads(const float* __restrict__ heads,
                              float* __restrict__ out_logits,
                              float* __restrict__ out_deltas) {
    int i = blockIdx.x * blockDim.x + threadIdx.x;
    if (i < N_ROI * NHEAD) {
        int r = i / NHEAD, c = i % NHEAD;
        float v = heads[(size_t)r * NHPAD + c];
        if (c < NCLS) out_logits[(size_t)r * NCLS + c] = v;
        else          out_deltas[(size_t)r * NDEL + (c - NCLS)] = v;
    }
}

__global__ void softmax_kernel(const float* __restrict__ logits,
                               float* __restrict__ probs, int M, int N) {
    int row  = blockIdx.x * (blockDim.x / 32) + threadIdx.x / 32;
    int lane = threadIdx.x & 31;
    if (row >= M) return;
    const float* lr = logits + (size_t)row * N;
    float v[3], mx = -1e30f;
#pragma unroll
    for (int j = 0; j < 3; j++) {
        int c = lane + j * 32;
        v[j] = (c < N) ? lr[c] : -1e30f;
        mx = fmaxf(mx, v[j]);
    }
#pragma unroll
    for (int o = 16; o; o >>= 1) mx = fmaxf(mx, __shfl_xor_sync(0xFFFFFFFFu, mx, o));
    float s = 0.f;
#pragma unroll
    for (int j = 0; j < 3; j++) {
        int c = lane + j * 32;
        v[j] = (c < N) ? expf(v[j] - mx) : 0.f;
        s += v[j];
    }
#pragma unroll
    for (int o = 16; o; o >>= 1) s += __shfl_xor_sync(0xFFFFFFFFu, s, o);
    float inv = 1.0f / s;
#pragma unroll
    for (int j = 0; j < 3; j++) {
        int c = lane + j * 32;
        if (c < N) probs[(size_t)row * N + c] = v[j] * inv;
    }
}

// ---------------------------------------------------------------------------
extern "C" void kernel_launch(void* const* d_in, const int* in_sizes, int n_in,
                              void* d_out, int out_size) {
    const float* pooled   = (const float*)d_in[0];
    const float* w1       = (const float*)d_in[1];
    const float* b1       = (const float*)d_in[2];
    const float* gamma1   = (const float*)d_in[3];
    const float* beta1    = (const float*)d_in[4];
    const float* w2       = (const float*)d_in[5];
    const float* b2       = (const float*)d_in[6];
    const float* gamma2   = (const float*)d_in[7];
    const float* beta2    = (const float*)d_in[8];
    const float* w_logits = (const float*)d_in[9];
    const float* b_logits = (const float*)d_in[10];
    const float* w_delta  = (const float*)d_in[11];
    const float* b_delta  = (const float*)d_in[12];

    float* out        = (float*)d_out;
    float* out_logits = out;
    float* out_probs  = out + N_ROI * NCLS;
    float* out_deltas = out + 2 * N_ROI * NCLS;

    float *At, *W1t, *W2t, *Wht, *bh, *x1, *x2, *heads, *scale, *shift;
    cudaGetSymbolAddress((void**)&At,    g_At);
    cudaGetSymbolAddress((void**)&W1t,   g_W1t);
    cudaGetSymbolAddress((void**)&W2t,   g_W2t);
    cudaGetSymbolAddress((void**)&Wht,   g_Wht);
    cudaGetSymbolAddress((void**)&bh,    g_bh);
    cudaGetSymbolAddress((void**)&x1,    g_x1);
    cudaGetSymbolAddress((void**)&x2,    g_x2);
    cudaGetSymbolAddress((void**)&heads, g_heads);
    cudaGetSymbolAddress((void**)&scale, g_scale);
    cudaGetSymbolAddress((void**)&shift, g_shift);

    cudaFuncSetAttribute(gemm_tf32, cudaFuncAttributeMaxDynamicSharedMemorySize, SMEM_TOT);

    // prep (5 launches so GEMM1 is launch #6 for ncu -s 5 -c 1)
    {
        int n4 = N_ROI * K1 / 4;
        cvt_rna_copy<<<(n4 + 255) / 256, 256>>>(pooled, At, n4);                     // 1
        dim3 tb(32, 8);
        transpose_rna<<<dim3(K1 / 32, HID / 32), tb>>>(w1, W1t, K1, HID, K1, 0);     // 2
        transpose_rna<<<dim3(HID / 32, HID / 32), tb>>>(w2, W2t, HID, HID, HID, 0);  // 3
        transpose_heads<<<dim3(HID / 32, (NHEAD + 31) / 32), tb>>>(w_logits, w_delta, Wht); // 4
        head_pad_init<<<64, 256>>>(b_logits, b_delta, bh, Wht);                      // 5
    }

    const int total = N_ROI * HID;
    dim3 bn_block(32, 8);
    dim3 g1(HID / 128, 16);

    gemm_tf32<<<g1, 128, SMEM_TOT>>>(At, W1t, b1, x1, N_ROI, K1, HID);               // 6 (profiled)
    bn_stats_kernel<<<HID / 32, bn_block>>>(x1, gamma1, beta1, scale, shift, N_ROI, HID);
    bn_relu_rna_kernel<<<(total + 255) / 256, 256>>>(x1, scale, shift, total, HID);

    gemm_tf32<<<g1, 128, SMEM_TOT>>>(x1, W2t, b2, x2, N_ROI, HID, HID);
    bn_stats_kernel<<<HID / 32, bn_block>>>(x2, gamma2, beta2, scale, shift, N_ROI, HID);
    bn_relu_rna_kernel<<<(total + 255) / 256, 256>>>(x2, scale, shift, total, HID);

    dim3 gh(NHPAD / 128, 16);
    gemm_tf32<<<gh, 128, SMEM_TOT>>>(x2, Wht, bh, heads, N_ROI, HID, NHPAD);
    scatter_heads<<<(N_ROI * NHEAD + 255) / 256, 256>>>(heads, out_logits, out_deltas);
    softmax_kernel<<<(N_ROI + 7) / 8, 256>>>(out_logits, out_probs, N_ROI, NCLS);
}

// round 6
// speedup vs baseline: 1.1698x; 1.1698x over previous
#include <cuda_runtime.h>
#include <cuda.h>
#include <mma.h>
#include <cstdint>

using namespace nvcuda;

// ---------------------------------------------------------------------------
// BBoxHead via tf32 WMMA GEMMs fed by 2D TMA (sm_90 features, compute_103-ok).
//   GEMM1: X[2000,12544] @ W1 -> x1 (+b1), BN+ReLU(+rna)
//   GEMM2: x1 @ W2 -> x2 (+b2), BN+ReLU(+rna)
//   HEADS: x2 @ [Wl|Wd] (N=512 padded) -> logits/deltas, softmax
// B operands pre-transposed to [N,K] K-major with cvt.rna.tf32.
// GEMM: 128x128 CTA tile, 8 warps, 32x64 warp tile, 5-stage TMA pipeline.
// ---------------------------------------------------------------------------

#define N_ROI  2000
#define K1     12544
#define HID    1024
#define NCLS   81
#define NDEL   324
#define NHEAD  405
#define NHPAD  512
#define BN_EPS 1e-3f

__device__ float g_At  [N_ROI * K1];
__device__ float g_W1t [HID * K1];
__device__ float g_W2t [HID * HID];
__device__ float g_Wht [NHPAD * HID];
__device__ float g_bh  [NHPAD];
__device__ float g_x1  [2048 * HID];
__device__ float g_x2  [2048 * HID];
__device__ float g_heads[N_ROI * NHPAD];
__device__ float g_scale[HID];
__device__ float g_shift[HID];

// ---------------------------------------------------------------------------
__device__ __forceinline__ uint32_t smem_u32(const void* p) {
    uint32_t a;
    asm("{ .reg .u64 t; cvta.to.shared.u64 t, %1; cvt.u32.u64 %0, t; }" : "=r"(a) : "l"(p));
    return a;
}
__device__ __forceinline__ float rna_tf32(float x) {
    uint32_t r;
    asm("cvt.rna.tf32.f32 %0, %1;" : "=r"(r) : "f"(x));
    return __uint_as_float(r);
}

#define MBAR_INIT(a, c)  asm volatile("mbarrier.init.shared.b64 [%0], %1;" :: "r"(a), "r"(c) : "memory")
#define MBAR_EXPECT_TX(a, b) asm volatile("mbarrier.arrive.expect_tx.shared.b64 _, [%0], %1;" :: "r"(a), "r"(b) : "memory")
#define MBAR_WAIT(a, ph) do {                                                     \
    uint32_t _m = (a); uint32_t _p = (ph);                                        \
    asm volatile("{\n\t.reg .pred P;\n\t"                                         \
        "WL_%=:\n\t"                                                              \
        "mbarrier.try_wait.parity.acquire.cta.shared::cta.b64 P, [%0], %1, 0x989680;\n\t" \
        "@P bra.uni WD_%=;\n\t"                                                   \
        "bra.uni WL_%=;\n\t"                                                      \
        "WD_%=:\n\t}" :: "r"(_m), "r"(_p) : "memory");                            \
} while (0)

#define TMA_LOAD_2D(saddr, mp, cx, cy, mb)                                        \
    asm volatile("cp.async.bulk.tensor.2d.shared::cta.global.tile.mbarrier::complete_tx::bytes " \
                 "[%0], [%1, {%2, %3}], [%4];"                                    \
                 :: "r"(saddr), "l"(mp), "r"(cx), "r"(cy), "r"(mb) : "memory")

// ---------------------------------------------------------------------------
// GEMM geometry / smem layout
//   tile row: 36 floats (32 data + 4 slack loaded by TMA box) = 144 B, LDT=36
//   stage: A tile 128*144 + B tile 128*144 = 36864 B; 5 stages
// ---------------------------------------------------------------------------
#define LDT      36
#define TILE_B   (128 * LDT * 4)          // 18432
#define STAGE_B  (2 * TILE_B)             // 36864
#define NSTAGE   5
#define SM_TILE0 1024
#define SMEM_TOT (SM_TILE0 + NSTAGE * STAGE_B)  // 185344
#define TXBYTES  STAGE_B
#define LDE      132

__global__ __launch_bounds__(256)
void gemm_tf32_tma(const __grid_constant__ CUtensorMap mapA,
                   const __grid_constant__ CUtensorMap mapB,
                   const float* __restrict__ bias, float* __restrict__ C,
                   int M, int K, int ldC) {
    extern __shared__ float smem_f[];
    const uint32_t sb = smem_u32(smem_f);
    const int tid = threadIdx.x;
    const int wid = tid >> 5;
    const int row0 = blockIdx.y * 128;
    const int col0 = blockIdx.x * 128;
    const int warp_m = wid & 3;     // 4 strips of 32 rows
    const int warp_n = wid >> 2;    // 2 strips of 64 cols
    const int NK = K / 32;

    if (tid == 0) {
#pragma unroll
        for (int s = 0; s < NSTAGE; s++) MBAR_INIT(sb + s * 8, 1);
    }
    __syncthreads();

    wmma::fragment<wmma::accumulator, 16, 16, 8, float> fc[2][4];
#pragma unroll
    for (int i = 0; i < 2; i++)
#pragma unroll
        for (int j = 0; j < 4; j++) wmma::fill_fragment(fc[i][j], 0.0f);

    // prologue: issue first NSTAGE-1 chunks
    if (tid == 0) {
        int pre = (NK < NSTAGE - 1) ? NK : NSTAGE - 1;
        for (int j = 0; j < pre; j++) {
            uint32_t st = sb + SM_TILE0 + j * STAGE_B;
            MBAR_EXPECT_TX(sb + j * 8, TXBYTES);
            TMA_LOAD_2D(st,          &mapA, j * 32, row0, sb + j * 8);
            TMA_LOAD_2D(st + TILE_B, &mapB, j * 32, col0, sb + j * 8);
        }
    }

    int s = 0, ph = 0;
    for (int i = 0; i < NK; i++) {
        MBAR_WAIT(sb + s * 8, ph);

        const float* As = smem_f + (SM_TILE0 + s * STAGE_B) / 4;
        const float* Bs = As + TILE_B / 4;
        const float* Aw = As + (warp_m * 32) * LDT;
        const float* Bw = Bs + (warp_n * 64) * LDT;

#pragma unroll
        for (int ks = 0; ks < 4; ks++) {
            wmma::fragment<wmma::matrix_a, 16, 16, 8, wmma::precision::tf32, wmma::row_major> fa[2];
            wmma::fragment<wmma::matrix_b, 16, 16, 8, wmma::precision::tf32, wmma::col_major> fb[4];
#pragma unroll
            for (int ii = 0; ii < 2; ii++)
                wmma::load_matrix_sync(fa[ii], Aw + ii * 16 * LDT + ks * 8, LDT);
#pragma unroll
            for (int jj = 0; jj < 4; jj++)
                wmma::load_matrix_sync(fb[jj], Bw + jj * 16 * LDT + ks * 8, LDT);
#pragma unroll
            for (int ii = 0; ii < 2; ii++)
#pragma unroll
                for (int jj = 0; jj < 4; jj++)
                    wmma::mma_sync(fc[ii][jj], fa[ii], fb[jj], fc[ii][jj]);
        }

        __syncthreads();   // all warps done with this stage (and stage being refilled)

        int nx = i + NSTAGE - 1;
        if (tid == 0 && nx < NK) {
            int sn = nx % NSTAGE;
            uint32_t st = sb + SM_TILE0 + sn * STAGE_B;
            MBAR_EXPECT_TX(sb + sn * 8, TXBYTES);
            TMA_LOAD_2D(st,          &mapA, nx * 32, row0, sb + sn * 8);
            TMA_LOAD_2D(st + TILE_B, &mapB, nx * 32, col0, sb + sn * 8);
        }
        if (++s == NSTAGE) { s = 0; ph ^= 1; }
    }

    // epilogue: frags -> smem -> global (+bias)
    float* esm = smem_f;
#pragma unroll
    for (int ii = 0; ii < 2; ii++)
#pragma unroll
        for (int jj = 0; jj < 4; jj++)
            wmma::store_matrix_sync(esm + (warp_m * 32 + ii * 16) * LDE + warp_n * 64 + jj * 16,
                                    fc[ii][jj], LDE, wmma::mem_row_major);
    __syncthreads();
#pragma unroll 4
    for (int e = tid; e < 128 * 32; e += 256) {
        int r  = e >> 5;
        int c4 = (e & 31) * 4;
        int gr = row0 + r;
        if (gr < M) {
            const float* sp = esm + r * LDE + c4;
            float4 v;
            v.x = sp[0] + bias[col0 + c4 + 0];
            v.y = sp[1] + bias[col0 + c4 + 1];
            v.z = sp[2] + bias[col0 + c4 + 2];
            v.w = sp[3] + bias[col0 + c4 + 3];
            *(float4*)&C[(size_t)gr * ldC + c4 + col0] = v;
        }
    }
}

// ---------------------------------------------------------------------------
// Prep kernels
// ---------------------------------------------------------------------------
__global__ void cvt_rna_copy(const float* __restrict__ in, float* __restrict__ out, int n4) {
    int i = blockIdx.x * blockDim.x + threadIdx.x;
    if (i < n4) {
        float4 v = ((const float4*)in)[i];
        v.x = rna_tf32(v.x); v.y = rna_tf32(v.y);
        v.z = rna_tf32(v.z); v.w = rna_tf32(v.w);
        ((float4*)out)[i] = v;
    }
}

// One kernel transposes+rna-converts all weights: w1, w2, and fused heads.
#define W1_BLKS  (392 * 32)   // 12544
#define W2_BLKS  (32 * 32)    // 1024
#define WH_BLKS  (32 * 13)    // 416
__global__ void prep_weights(const float* __restrict__ w1, const float* __restrict__ w2,
                             const float* __restrict__ wl, const float* __restrict__ wd,
                             float* __restrict__ W1t, float* __restrict__ W2t,
                             float* __restrict__ Wht) {
    __shared__ float t[32][33];
    int b = blockIdx.x;
    int x = threadIdx.x, y = threadIdx.y;

    if (b < W1_BLKS) {                       // w1 [12544,1024] -> W1t [1024,12544]
        int kblk = b % 392, nblk = b / 392;
        int k0 = kblk * 32, n0 = nblk * 32;
#pragma unroll
        for (int yy = y; yy < 32; yy += 8)
            t[yy][x] = w1[(size_t)(k0 + yy) * HID + n0 + x];
        __syncthreads();
#pragma unroll
        for (int yy = y; yy < 32; yy += 8)
            W1t[(size_t)(n0 + yy) * K1 + k0 + x] = rna_tf32(t[x][yy]);
    } else if (b < W1_BLKS + W2_BLKS) {      // w2 [1024,1024] -> W2t [1024,1024]
        int b2 = b - W1_BLKS;
        int kblk = b2 % 32, nblk = b2 / 32;
        int k0 = kblk * 32, n0 = nblk * 32;
#pragma unroll
        for (int yy = y; yy < 32; yy += 8)
            t[yy][x] = w2[(size_t)(k0 + yy) * HID + n0 + x];
        __syncthreads();
#pragma unroll
        for (int yy = y; yy < 32; yy += 8)
            W2t[(size_t)(n0 + yy) * HID + k0 + x] = rna_tf32(t[x][yy]);
    } else {                                 // [wl|wd] -> Wht rows 0..404
        int b3 = b - W1_BLKS - W2_BLKS;
        int kblk = b3 % 32, nblk = b3 / 32;
        int k0 = kblk * 32, n0 = nblk * 32;
#pragma unroll
        for (int yy = y; yy < 32; yy += 8) {
            int k = k0 + yy, n = n0 + x;
            float v = 0.f;
            if (n < NHEAD)
                v = (n < NCLS) ? wl[(size_t)k * NCLS + n]
                               : wd[(size_t)k * NDEL + (n - NCLS)];
            t[yy][x] = v;
        }
        __syncthreads();
#pragma unroll
        for (int yy = y; yy < 32; yy += 8) {
            int n = n0 + yy, k = k0 + x;
            if (n < NHEAD)
                Wht[(size_t)n * HID + k] = rna_tf32(t[x][yy]);
        }
    }
}

__global__ void bh_init(const float* __restrict__ bl, const float* __restrict__ bd,
                        float* __restrict__ bh) {
    int i = blockIdx.x * blockDim.x + threadIdx.x;
    if (i < NHPAD)
        bh[i] = (i < NCLS) ? bl[i] : (i < NHEAD ? bd[i - NCLS] : 0.f);
}

// ---------------------------------------------------------------------------
// BN / activation / heads epilogue
// ---------------------------------------------------------------------------
__global__ void bn_stats_kernel(const float* __restrict__ x,
                                const float* __restrict__ gamma,
                                const float* __restrict__ beta,
                                float* __restrict__ scale, float* __restrict__ shift,
                                int M, int N) {
    int col = blockIdx.x * 32 + threadIdx.x;
    float s = 0.f, sq = 0.f;
    for (int r = threadIdx.y; r < M; r += blockDim.y) {
        float v = x[(size_t)r * N + col];
        s += v; sq += v * v;
    }
    __shared__ float ss[8][32], sg[8][32];
    ss[threadIdx.y][threadIdx.x] = s;
    sg[threadIdx.y][threadIdx.x] = sq;
    __syncthreads();
    if (threadIdx.y == 0) {
#pragma unroll
        for (int i = 1; i < 8; i++) { s += ss[i][threadIdx.x]; sq += sg[i][threadIdx.x]; }
        float mean = s / (float)M;
        float var  = sq / (float)M - mean * mean;
        float sc   = gamma[col] * rsqrtf(var + BN_EPS);
        scale[col] = sc;
        shift[col] = beta[col] - mean * sc;
    }
}

__global__ void bn_relu_rna_kernel(float* __restrict__ x, const float* __restrict__ scale,
                                   const float* __restrict__ shift, int total, int N) {
    int i = blockIdx.x * blockDim.x + threadIdx.x;
    if (i < total) {
        int c = i & (N - 1);
        x[i] = rna_tf32(fmaxf(0.f, fmaf(x[i], scale[c], shift[c])));
    }
}

__global__ void scatter_heads(const float* __restrict__ heads,
                              float* __restrict__ out_logits,
                              float* __restrict__ out_deltas) {
    int i = blockIdx.x * blockDim.x + threadIdx.x;
    if (i < N_ROI * NHEAD) {
        int r = i / NHEAD, c = i % NHEAD;
        float v = heads[(size_t)r * NHPAD + c];
        if (c < NCLS) out_logits[(size_t)r * NCLS + c] = v;
        else          out_deltas[(size_t)r * NDEL + (c - NCLS)] = v;
    }
}

__global__ void softmax_kernel(const float* __restrict__ logits,
                               float* __restrict__ probs, int M, int N) {
    int row  = blockIdx.x * (blockDim.x / 32) + threadIdx.x / 32;
    int lane = threadIdx.x & 31;
    if (row >= M) return;
    const float* lr = logits + (size_t)row * N;
    float v[3], mx = -1e30f;
#pragma unroll
    for (int j = 0; j < 3; j++) {
        int c = lane + j * 32;
        v[j] = (c < N) ? lr[c] : -1e30f;
        mx = fmaxf(mx, v[j]);
    }
#pragma unroll
    for (int o = 16; o; o >>= 1) mx = fmaxf(mx, __shfl_xor_sync(0xFFFFFFFFu, mx, o));
    float s = 0.f;
#pragma unroll
    for (int j = 0; j < 3; j++) {
        int c = lane + j * 32;
        v[j] = (c < N) ? expf(v[j] - mx) : 0.f;
        s += v[j];
    }
#pragma unroll
    for (int o = 16; o; o >>= 1) s += __shfl_xor_sync(0xFFFFFFFFu, s, o);
    float inv = 1.0f / s;
#pragma unroll
    for (int j = 0; j < 3; j++) {
        int c = lane + j * 32;
        if (c < N) probs[(size_t)row * N + c] = v[j] * inv;
    }
}

// ---------------------------------------------------------------------------
// Host: tensormap construction via driver entry point (no -lcuda needed)
// ---------------------------------------------------------------------------
typedef CUresult (*EncodeTiledFn)(CUtensorMap*, CUtensorMapDataType, cuuint32_t,
                                  void*, const cuuint64_t*, const cuuint64_t*,
                                  const cuuint32_t*, const cuuint32_t*,
                                  CUtensorMapInterleave, CUtensorMapSwizzle,
                                  CUtensorMapL2promotion, CUtensorMapFloatOOBfill);

static void make_map2d(EncodeTiledFn enc, CUtensorMap* m, void* ptr,
                       uint64_t kdim, uint64_t rows) {
    cuuint64_t dims[2]    = {kdim, rows};
    cuuint64_t strides[1] = {kdim * 4};
    cuuint32_t box[2]     = {36, 128};
    cuuint32_t estr[2]    = {1, 1};
    enc(m, CU_TENSOR_MAP_DATA_TYPE_FLOAT32, 2, ptr, dims, strides, box, estr,
        CU_TENSOR_MAP_INTERLEAVE_NONE, CU_TENSOR_MAP_SWIZZLE_NONE,
        CU_TENSOR_MAP_L2_PROMOTION_L2_128B, CU_TENSOR_MAP_FLOAT_OOB_FILL_NONE);
}

extern "C" void kernel_launch(void* const* d_in, const int* in_sizes, int n_in,
                              void* d_out, int out_size) {
    const float* pooled   = (const float*)d_in[0];
    const float* w1       = (const float*)d_in[1];
    const float* b1       = (const float*)d_in[2];
    const float* gamma1   = (const float*)d_in[3];
    const float* beta1    = (const float*)d_in[4];
    const float* w2       = (const float*)d_in[5];
    const float* b2       = (const float*)d_in[6];
    const float* gamma2   = (const float*)d_in[7];
    const float* beta2    = (const float*)d_in[8];
    const float* w_logits = (const float*)d_in[9];
    const float* b_logits = (const float*)d_in[10];
    const float* w_delta  = (const float*)d_in[11];
    const float* b_delta  = (const float*)d_in[12];

    float* out        = (float*)d_out;
    float* out_logits = out;
    float* out_probs  = out + N_ROI * NCLS;
    float* out_deltas = out + 2 * N_ROI * NCLS;

    float *At, *W1t, *W2t, *Wht, *bh, *x1, *x2, *heads, *scale, *shift;
    cudaGetSymbolAddress((void**)&At,    g_At);
    cudaGetSymbolAddress((void**)&W1t,   g_W1t);
    cudaGetSymbolAddress((void**)&W2t,   g_W2t);
    cudaGetSymbolAddress((void**)&Wht,   g_Wht);
    cudaGetSymbolAddress((void**)&bh,    g_bh);
    cudaGetSymbolAddress((void**)&x1,    g_x1);
    cudaGetSymbolAddress((void**)&x2,    g_x2);
    cudaGetSymbolAddress((void**)&heads, g_heads);
    cudaGetSymbolAddress((void**)&scale, g_scale);
    cudaGetSymbolAddress((void**)&shift, g_shift);

    // driver entry point for tensormap encode
    EncodeTiledFn enc = nullptr;
#if CUDART_VERSION >= 12000
    cudaDriverEntryPointQueryResult qr;
    cudaGetDriverEntryPoint("cuTensorMapEncodeTiled", (void**)&enc,
                            cudaEnableDefault, &qr);
#else
    cudaGetDriverEntryPoint("cuTensorMapEncodeTiled", (void**)&enc, cudaEnableDefault);
#endif

    CUtensorMap mA1, mB1, mA2, mB2, mA3, mB3;
    make_map2d(enc, &mA1, At,  K1,  N_ROI);
    make_map2d(enc, &mB1, W1t, K1,  HID);
    make_map2d(enc, &mA2, x1,  HID, N_ROI);
    make_map2d(enc, &mB2, W2t, HID, HID);
    make_map2d(enc, &mA3, x2,  HID, N_ROI);
    make_map2d(enc, &mB3, Wht, HID, NHEAD);

    cudaFuncSetAttribute(gemm_tf32_tma, cudaFuncAttributeMaxDynamicSharedMemorySize, SMEM_TOT);

    // prep: 3 launches so GEMM1 is launch #4 (profiled by ncu)
    int n4 = N_ROI * K1 / 4;
    cvt_rna_copy<<<(n4 + 255) / 256, 256>>>(pooled, At, n4);                         // 1
    prep_weights<<<W1_BLKS + W2_BLKS + WH_BLKS, dim3(32, 8)>>>(w1, w2, w_logits, w_delta,
                                                               W1t, W2t, Wht);       // 2
    bh_init<<<2, 256>>>(b_logits, b_delta, bh);                                      // 3

    const int total = N_ROI * HID;
    dim3 bn_block(32, 8);
    dim3 g1(HID / 128, 16);

    gemm_tf32_tma<<<g1, 256, SMEM_TOT>>>(mA1, mB1, b1, x1, N_ROI, K1, HID);          // 4 (profiled)
    bn_stats_kernel<<<HID / 32, bn_block>>>(x1, gamma1, beta1, scale, shift, N_ROI, HID);
    bn_relu_rna_kernel<<<(total + 255) / 256, 256>>>(x1, scale, shift, total, HID);

    gemm_tf32_tma<<<g1, 256, SMEM_TOT>>>(mA2, mB2, b2, x2, N_ROI, HID, HID);
    bn_stats_kernel<<<HID / 32, bn_block>>>(x2, gamma2, beta2, scale, shift, N_ROI, HID);
    bn_relu_rna_kernel<<<(total + 255) / 256, 256>>>(x2, scale, shift, total, HID);

    dim3 gh(NHPAD / 128, 16);
    gemm_tf32_tma<<<gh, 256, SMEM_TOT>>>(mA3, mB3, bh, heads, N_ROI, HID, NHPAD);
    scatter_heads<<<(N_ROI * NHEAD + 255) / 256, 256>>>(heads, out_logits, out_deltas);
    softmax_kernel<<<(N_ROI + 7) / 8, 256>>>(out_logits, out_probs, N_ROI, NCLS);
}

// round 7
// speedup vs baseline: 1.2161x; 1.0396x over previous
#include <cuda_runtime.h>
#include <cuda.h>
#include <mma.h>
#include <cstdint>

using namespace nvcuda;

// ---------------------------------------------------------------------------
// BBoxHead via tf32 WMMA GEMMs, TMA-fed, warp-specialized pipeline.
//   GEMM1: pooled[2000,12544] @ W1 -> x1 (+b1), BN+ReLU
//   GEMM2: x1 @ W2 -> x2 (+b2), BN+ReLU
//   HEADS: x2 @ [Wl|Wd] (N=512 pad) -> logits/deltas, softmax
// B operands pre-transposed to [N,K] K-major with cvt.rna.tf32;
// A operands rna-converted in-register after fragment load.
// GEMM: 128x128 CTA tile, 8 consumer warps (32x64 each) + 1 TMA producer warp,
// 5-stage mbarrier pipeline, NO mainloop __syncthreads.
// ---------------------------------------------------------------------------

#define N_ROI  2000
#define K1     12544
#define HID    1024
#define NCLS   81
#define NDEL   324
#define NHEAD  405
#define NHPAD  512
#define BN_EPS 1e-3f

__device__ float g_W1t [HID * K1];
__device__ float g_W2t [HID * HID];
__device__ float g_Wht [NHPAD * HID];
__device__ float g_bh  [NHPAD];
__device__ float g_x1  [2048 * HID];
__device__ float g_x2  [2048 * HID];
__device__ float g_heads[N_ROI * NHPAD];
__device__ float g_scale[HID];
__device__ float g_shift[HID];

// ---------------------------------------------------------------------------
__device__ __forceinline__ uint32_t smem_u32(const void* p) {
    uint32_t a;
    asm("{ .reg .u64 t; cvta.to.shared.u64 t, %1; cvt.u32.u64 %0, t; }" : "=r"(a) : "l"(p));
    return a;
}
__device__ __forceinline__ float rna_tf32(float x) {
    uint32_t r;
    asm("cvt.rna.tf32.f32 %0, %1;" : "=r"(r) : "f"(x));
    return __uint_as_float(r);
}

#define MBAR_INIT(a, c)      asm volatile("mbarrier.init.shared.b64 [%0], %1;" :: "r"(a), "r"(c) : "memory")
#define MBAR_EXPECT_TX(a, b) asm volatile("mbarrier.arrive.expect_tx.shared.b64 _, [%0], %1;" :: "r"(a), "r"(b) : "memory")
#define MBAR_ARRIVE(a)       asm volatile("mbarrier.arrive.shared.b64 _, [%0];" :: "r"(a) : "memory")
#define MBAR_WAIT(a, ph) do {                                                     \
    uint32_t _m = (a); uint32_t _p = (ph);                                        \
    asm volatile("{\n\t.reg .pred P;\n\t"                                         \
        "WL_%=:\n\t"                                                              \
        "mbarrier.try_wait.parity.acquire.cta.shared::cta.b64 P, [%0], %1, 0x989680;\n\t" \
        "@P bra.uni WD_%=;\n\t"                                                   \
        "bra.uni WL_%=;\n\t"                                                      \
        "WD_%=:\n\t}" :: "r"(_m), "r"(_p) : "memory");                            \
} while (0)

#define TMA_LOAD_2D(saddr, mp, cx, cy, mb)                                        \
    asm volatile("cp.async.bulk.tensor.2d.shared::cta.global.tile.mbarrier::complete_tx::bytes " \
                 "[%0], [%1, {%2, %3}], [%4];"                                    \
                 :: "r"(saddr), "l"(mp), "r"(cx), "r"(cy), "r"(mb) : "memory")

// ---------------------------------------------------------------------------
// Geometry: tile row = 36 floats (32 data + 4 TMA slack) = 144 B.
// stage = A(128x144B) + B(128x144B) = 36864 B; 5 stages.
// Barriers: full[s] at sb+s*16, empty[s] at sb+s*16+8. Tiles from offset 1024.
// ---------------------------------------------------------------------------
#define LDT      36
#define TILE_B   (128 * LDT * 4)
#define STAGE_B  (2 * TILE_B)
#define NSTAGE   5
#define SM_TILE0 1024
#define SMEM_TOT (SM_TILE0 + NSTAGE * STAGE_B)   // 185344
#define TXBYTES  STAGE_B
#define LDE      132
#define NTHREADS 288                              // 8 consumer warps + 1 producer

__global__ __launch_bounds__(NTHREADS)
void gemm_tf32_tma(const __grid_constant__ CUtensorMap mapA,
                   const __grid_constant__ CUtensorMap mapB,
                   const float* __restrict__ bias, float* __restrict__ C,
                   int M, int K, int ldC) {
    extern __shared__ float smem_f[];
    const uint32_t sb = smem_u32(smem_f);
    const int tid  = threadIdx.x;
    const int wid  = tid >> 5;
    const int lane = tid & 31;
    const int row0 = blockIdx.y * 128;
    const int col0 = blockIdx.x * 128;
    const int NK = K / 32;

    if (tid == 0) {
#pragma unroll
        for (int s = 0; s < NSTAGE; s++) {
            MBAR_INIT(sb + s * 16,     1);   // full: tx-based
            MBAR_INIT(sb + s * 16 + 8, 8);   // empty: 8 consumer warps
        }
    }
    __syncthreads();

    if (wid == 8) {
        // ---- producer warp: lane 0 issues TMA for all chunks ----
        if (lane == 0) {
            int s = 0, ph = 1;                 // phase-flip trick: first waits pass
            for (int i = 0; i < NK; i++) {
                MBAR_WAIT(sb + s * 16 + 8, ph);
                uint32_t st = sb + SM_TILE0 + s * STAGE_B;
                MBAR_EXPECT_TX(sb + s * 16, TXBYTES);
                TMA_LOAD_2D(st,          &mapA, i * 32, row0, sb + s * 16);
                TMA_LOAD_2D(st + TILE_B, &mapB, i * 32, col0, sb + s * 16);
                if (++s == NSTAGE) { s = 0; ph ^= 1; }
            }
        }
    } else {
        // ---- consumer warps ----
        const int warp_m = wid & 3;    // 4 strips of 32 rows
        const int warp_n = wid >> 2;   // 2 strips of 64 cols

        wmma::fragment<wmma::accumulator, 16, 16, 8, float> fc[2][4];
#pragma unroll
        for (int i = 0; i < 2; i++)
#pragma unroll
            for (int j = 0; j < 4; j++) wmma::fill_fragment(fc[i][j], 0.0f);

        int s = 0, ph = 0;
        for (int i = 0; i < NK; i++) {
            MBAR_WAIT(sb + s * 16, ph);

            const float* As = smem_f + (SM_TILE0 + s * STAGE_B) / 4;
            const float* Bs = As + TILE_B / 4;
            const float* Aw = As + (warp_m * 32) * LDT;
            const float* Bw = Bs + (warp_n * 64) * LDT;

            // ks-level double-buffered fragments
            wmma::fragment<wmma::matrix_a, 16, 16, 8, wmma::precision::tf32, wmma::row_major> fa[2][2];
            wmma::fragment<wmma::matrix_b, 16, 16, 8, wmma::precision::tf32, wmma::col_major> fb[2][4];

#pragma unroll
            for (int ii = 0; ii < 2; ii++) {
                wmma::load_matrix_sync(fa[0][ii], Aw + ii * 16 * LDT, LDT);
#pragma unroll
                for (int t = 0; t < fa[0][ii].num_elements; t++)
                    fa[0][ii].x[t] = rna_tf32(fa[0][ii].x[t]);
            }
#pragma unroll
            for (int jj = 0; jj < 4; jj++)
                wmma::load_matrix_sync(fb[0][jj], Bw + jj * 16 * LDT, LDT);

#pragma unroll
            for (int ks = 0; ks < 4; ks++) {
                int cur = ks & 1, nxt = cur ^ 1;
                if (ks < 3) {
#pragma unroll
                    for (int ii = 0; ii < 2; ii++) {
                        wmma::load_matrix_sync(fa[nxt][ii], Aw + ii * 16 * LDT + (ks + 1) * 8, LDT);
#pragma unroll
                        for (int t = 0; t < fa[nxt][ii].num_elements; t++)
                            fa[nxt][ii].x[t] = rna_tf32(fa[nxt][ii].x[t]);
                    }
#pragma unroll
                    for (int jj = 0; jj < 4; jj++)
                        wmma::load_matrix_sync(fb[nxt][jj], Bw + jj * 16 * LDT + (ks + 1) * 8, LDT);
                }
#pragma unroll
                for (int ii = 0; ii < 2; ii++)
#pragma unroll
                    for (int jj = 0; jj < 4; jj++)
                        wmma::mma_sync(fc[ii][jj], fa[cur][ii], fb[cur][jj], fc[ii][jj]);
            }

            if (lane == 0) MBAR_ARRIVE(sb + s * 16 + 8);
            if (++s == NSTAGE) { s = 0; ph ^= 1; }
        }

        // stash accumulators to smem after ALL warps/TMA are done (barrier below)
        __syncthreads();
        float* esm = smem_f;
#pragma unroll
        for (int ii = 0; ii < 2; ii++)
#pragma unroll
            for (int jj = 0; jj < 4; jj++)
                wmma::store_matrix_sync(esm + (warp_m * 32 + ii * 16) * LDE + warp_n * 64 + jj * 16,
                                        fc[ii][jj], LDE, wmma::mem_row_major);
    }
    if (wid == 8) __syncthreads();   // producer joins the pre-epilogue barrier
    __syncthreads();                 // esm ready

    const float* esm = smem_f;
#pragma unroll 2
    for (int e = tid; e < 128 * 32; e += NTHREADS) {
        int r  = e >> 5;
        int c4 = (e & 31) * 4;
        int gr = row0 + r;
        if (gr < M) {
            const float* sp = esm + r * LDE + c4;
            float4 v;
            v.x = sp[0] + bias[col0 + c4 + 0];
            v.y = sp[1] + bias[col0 + c4 + 1];
            v.z = sp[2] + bias[col0 + c4 + 2];
            v.w = sp[3] + bias[col0 + c4 + 3];
            *(float4*)&C[(size_t)gr * ldC + col0 + c4] = v;
        }
    }
}

// ---------------------------------------------------------------------------
// Prep kernels (weights transpose + rna)
// ---------------------------------------------------------------------------
#define W1_BLKS  (392 * 32)
#define W2_BLKS  (32 * 32)
__global__ void prep_w12(const float* __restrict__ w1, const float* __restrict__ w2,
                         float* __restrict__ W1t, float* __restrict__ W2t) {
    __shared__ float t[32][33];
    int b = blockIdx.x;
    int x = threadIdx.x, y = threadIdx.y;
    if (b < W1_BLKS) {
        int kblk = b % 392, nblk = b / 392;
        int k0 = kblk * 32, n0 = nblk * 32;
#pragma unroll
        for (int yy = y; yy < 32; yy += 8)
            t[yy][x] = w1[(size_t)(k0 + yy) * HID + n0 + x];
        __syncthreads();
#pragma unroll
        for (int yy = y; yy < 32; yy += 8)
            W1t[(size_t)(n0 + yy) * K1 + k0 + x] = rna_tf32(t[x][yy]);
    } else {
        int b2 = b - W1_BLKS;
        int kblk = b2 % 32, nblk = b2 / 32;
        int k0 = kblk * 32, n0 = nblk * 32;
#pragma unroll
        for (int yy = y; yy < 32; yy += 8)
            t[yy][x] = w2[(size_t)(k0 + yy) * HID + n0 + x];
        __syncthreads();
#pragma unroll
        for (int yy = y; yy < 32; yy += 8)
            W2t[(size_t)(n0 + yy) * HID + k0 + x] = rna_tf32(t[x][yy]);
    }
}

__global__ void prep_heads(const float* __restrict__ wl, const float* __restrict__ wd,
                           float* __restrict__ Wht) {
    __shared__ float t[32][33];
    int kblk = blockIdx.x % 32, nblk = blockIdx.x / 32;
    int k0 = kblk * 32, n0 = nblk * 32;
    int x = threadIdx.x, y = threadIdx.y;
#pragma unroll
    for (int yy = y; yy < 32; yy += 8) {
        int k = k0 + yy, n = n0 + x;
        float v = 0.f;
        if (n < NHEAD)
            v = (n < NCLS) ? wl[(size_t)k * NCLS + n]
                           : wd[(size_t)k * NDEL + (n - NCLS)];
        t[yy][x] = v;
    }
    __syncthreads();
#pragma unroll
    for (int yy = y; yy < 32; yy += 8) {
        int n = n0 + yy, k = k0 + x;
        if (n < NHEAD)
            Wht[(size_t)n * HID + k] = rna_tf32(t[x][yy]);
    }
}

__global__ void bh_init(const float* __restrict__ bl, const float* __restrict__ bd,
                        float* __restrict__ bh) {
    int i = blockIdx.x * blockDim.x + threadIdx.x;
    if (i < NHPAD)
        bh[i] = (i < NCLS) ? bl[i] : (i < NHEAD ? bd[i - NCLS] : 0.f);
}

// ---------------------------------------------------------------------------
// BN / activation / heads epilogue
// ---------------------------------------------------------------------------
__global__ void bn_stats_kernel(const float* __restrict__ x,
                                const float* __restrict__ gamma,
                                const float* __restrict__ beta,
                                float* __restrict__ scale, float* __restrict__ shift,
                                int M, int N) {
    int col = blockIdx.x * 32 + threadIdx.x;
    float s = 0.f, sq = 0.f;
    for (int r = threadIdx.y; r < M; r += blockDim.y) {
        float v = x[(size_t)r * N + col];
        s += v; sq += v * v;
    }
    __shared__ float ss[8][32], sg[8][32];
    ss[threadIdx.y][threadIdx.x] = s;
    sg[threadIdx.y][threadIdx.x] = sq;
    __syncthreads();
    if (threadIdx.y == 0) {
#pragma unroll
        for (int i = 1; i < 8; i++) { s += ss[i][threadIdx.x]; sq += sg[i][threadIdx.x]; }
        float mean = s / (float)M;
        float var  = sq / (float)M - mean * mean;
        float sc   = gamma[col] * rsqrtf(var + BN_EPS);
        scale[col] = sc;
        shift[col] = beta[col] - mean * sc;
    }
}

__global__ void bn_relu_kernel(float* __restrict__ x, const float* __restrict__ scale,
                               const float* __restrict__ shift, int total, int N) {
    int i = blockIdx.x * blockDim.x + threadIdx.x;
    if (i < total) {
        int c = i & (N - 1);
        x[i] = fmaxf(0.f, fmaf(x[i], scale[c], shift[c]));
    }
}

__global__ void scatter_heads(const float* __restrict__ heads,
                              float* __restrict__ out_logits,
                              float* __restrict__ out_deltas) {
    int i = blockIdx.x * blockDim.x + threadIdx.x;
    if (i < N_ROI * NHEAD) {
        int r = i / NHEAD, c = i % NHEAD;
        float v = heads[(size_t)r * NHPAD + c];
        if (c < NCLS) out_logits[(size_t)r * NCLS + c] = v;
        else          out_deltas[(size_t)r * NDEL + (c - NCLS)] = v;
    }
}

__global__ void softmax_kernel(const float* __restrict__ logits,
                               float* __restrict__ probs, int M, int N) {
    int row  = blockIdx.x * (blockDim.x / 32) + threadIdx.x / 32;
    int lane = threadIdx.x & 31;
    if (row >= M) return;
    const float* lr = logits + (size_t)row * N;
    float v[3], mx = -1e30f;
#pragma unroll
    for (int j = 0; j < 3; j++) {
        int c = lane + j * 32;
        v[j] = (c < N) ? lr[c] : -1e30f;
        mx = fmaxf(mx, v[j]);
    }
#pragma unroll
    for (int o = 16; o; o >>= 1) mx = fmaxf(mx, __shfl_xor_sync(0xFFFFFFFFu, mx, o));
    float s = 0.f;
#pragma unroll
    for (int j = 0; j < 3; j++) {
        int c = lane + j * 32;
        v[j] = (c < N) ? expf(v[j] - mx) : 0.f;
        s += v[j];
    }
#pragma unroll
    for (int o = 16; o; o >>= 1) s += __shfl_xor_sync(0xFFFFFFFFu, s, o);
    float inv = 1.0f / s;
#pragma unroll
    for (int j = 0; j < 3; j++) {
        int c = lane + j * 32;
        if (c < N) probs[(size_t)row * N + c] = v[j] * inv;
    }
}

// ---------------------------------------------------------------------------
typedef CUresult (*EncodeTiledFn)(CUtensorMap*, CUtensorMapDataType, cuuint32_t,
                                  void*, const cuuint64_t*, const cuuint64_t*,
                                  const cuuint32_t*, const cuuint32_t*,
                                  CUtensorMapInterleave, CUtensorMapSwizzle,
                                  CUtensorMapL2promotion, CUtensorMapFloatOOBfill);

static void make_map2d(EncodeTiledFn enc, CUtensorMap* m, void* ptr,
                       uint64_t kdim, uint64_t rows) {
    cuuint64_t dims[2]    = {kdim, rows};
    cuuint64_t strides[1] = {kdim * 4};
    cuuint32_t box[2]     = {36, 128};
    cuuint32_t estr[2]    = {1, 1};
    enc(m, CU_TENSOR_MAP_DATA_TYPE_FLOAT32, 2, ptr, dims, strides, box, estr,
        CU_TENSOR_MAP_INTERLEAVE_NONE, CU_TENSOR_MAP_SWIZZLE_NONE,
        CU_TENSOR_MAP_L2_PROMOTION_L2_128B, CU_TENSOR_MAP_FLOAT_OOB_FILL_NONE);
}

extern "C" void kernel_launch(void* const* d_in, const int* in_sizes, int n_in,
                              void* d_out, int out_size) {
    const float* pooled   = (const float*)d_in[0];
    const float* w1       = (const float*)d_in[1];
    const float* b1       = (const float*)d_in[2];
    const float* gamma1   = (const float*)d_in[3];
    const float* beta1    = (const float*)d_in[4];
    const float* w2       = (const float*)d_in[5];
    const float* b2       = (const float*)d_in[6];
    const float* gamma2   = (const float*)d_in[7];
    const float* beta2    = (const float*)d_in[8];
    const float* w_logits = (const float*)d_in[9];
    const float* b_logits = (const float*)d_in[10];
    const float* w_delta  = (const float*)d_in[11];
    const float* b_delta  = (const float*)d_in[12];

    float* out        = (float*)d_out;
    float* out_logits = out;
    float* out_probs  = out + N_ROI * NCLS;
    float* out_deltas = out + 2 * N_ROI * NCLS;

    float *W1t, *W2t, *Wht, *bh, *x1, *x2, *heads, *scale, *shift;
    cudaGetSymbolAddress((void**)&W1t,   g_W1t);
    cudaGetSymbolAddress((void**)&W2t,   g_W2t);
    cudaGetSymbolAddress((void**)&Wht,   g_Wht);
    cudaGetSymbolAddress((void**)&bh,    g_bh);
    cudaGetSymbolAddress((void**)&x1,    g_x1);
    cudaGetSymbolAddress((void**)&x2,    g_x2);
    cudaGetSymbolAddress((void**)&heads, g_heads);
    cudaGetSymbolAddress((void**)&scale, g_scale);
    cudaGetSymbolAddress((void**)&shift, g_shift);

    EncodeTiledFn enc = nullptr;
#if CUDART_VERSION >= 12000
    cudaDriverEntryPointQueryResult qr;
    cudaGetDriverEntryPoint("cuTensorMapEncodeTiled", (void**)&enc,
                            cudaEnableDefault, &qr);
#else
    cudaGetDriverEntryPoint("cuTensorMapEncodeTiled", (void**)&enc, cudaEnableDefault);
#endif

    CUtensorMap mA1, mB1, mA2, mB2, mA3, mB3;
    make_map2d(enc, &mA1, (void*)pooled, K1,  N_ROI);
    make_map2d(enc, &mB1, W1t, K1,  HID);
    make_map2d(enc, &mA2, x1,  HID, N_ROI);
    make_map2d(enc, &mB2, W2t, HID, HID);
    make_map2d(enc, &mA3, x2,  HID, N_ROI);
    make_map2d(enc, &mB3, Wht, HID, NHEAD);

    cudaFuncSetAttribute(gemm_tf32_tma, cudaFuncAttributeMaxDynamicSharedMemorySize, SMEM_TOT);

    // prep: 3 launches so GEMM1 is launch #4 (the one ncu profiles)
    prep_w12<<<W1_BLKS + W2_BLKS, dim3(32, 8)>>>(w1, w2, W1t, W2t);                  // 1
    prep_heads<<<32 * 13, dim3(32, 8)>>>(w_logits, w_delta, Wht);                    // 2
    bh_init<<<2, 256>>>(b_logits, b_delta, bh);                                      // 3

    const int total = N_ROI * HID;
    dim3 bn_block(32, 8);
    dim3 g1(HID / 128, 16);

    gemm_tf32_tma<<<g1, NTHREADS, SMEM_TOT>>>(mA1, mB1, b1, x1, N_ROI, K1, HID);     // 4 (profiled)
    bn_stats_kernel<<<HID / 32, bn_block>>>(x1, gamma1, beta1, scale, shift, N_ROI, HID);
    bn_relu_kernel<<<(total + 255) / 256, 256>>>(x1, scale, shift, total, HID);

    gemm_tf32_tma<<<g1, NTHREADS, SMEM_TOT>>>(mA2, mB2, b2, x2, N_ROI, HID, HID);
    bn_stats_kernel<<<HID / 32, bn_block>>>(x2, gamma2, beta2, scale, shift, N_ROI, HID);
    bn_relu_kernel<<<(total + 255) / 256, 256>>>(x2, scale, shift, total, HID);

    dim3 gh(NHPAD / 128, 16);
    gemm_tf32_tma<<<gh, NTHREADS, SMEM_TOT>>>(mA3, mB3, bh, heads, N_ROI, HID, NHPAD);
    scatter_heads<<<(N_ROI * NHEAD + 255) / 256, 256>>>(heads, out_logits, out_deltas);
    softmax_kernel<<<(N_ROI + 7) / 8, 256>>>(out_logits, out_probs, N_ROI, NCLS);
}